// round 4
// baseline (speedup 1.0000x reference)
#include <cuda_runtime.h>
#include <math.h>

// Problem constants
#define Bsz 16
#define Nn  16384
#define Cc  128          // C_IN == C_OUT
#define Kk  9
#define Ff  1152         // Kk * Cc
#define Mm  (Bsz * Nn)   // 262144 rows

// Static device scratch (no runtime allocation allowed)
__device__ float g_flat[(size_t)Mm * Ff];   // elu(P @ gathered x), (B*N, 1152)
__device__ float g_Wt[Ff * Cc];             // W_conv transposed: [f][o]
__device__ float g_Wst[Cc * Cc];            // W_skip transposed: [c][o]

typedef unsigned long long ull;

// ---- packed f32x2 helpers (FFMA2 path: ptxas never emits from C++) ----
__device__ __forceinline__ ull pack2(float lo, float hi) {
    ull r;
    asm("mov.b64 %0,{%1,%2};" : "=l"(r)
        : "r"(__float_as_uint(lo)), "r"(__float_as_uint(hi)));
    return r;
}
__device__ __forceinline__ float2 unpack2(ull v) {
    unsigned lo, hi;
    asm("mov.b64 {%0,%1},%2;" : "=r"(lo), "=r"(hi) : "l"(v));
    return make_float2(__uint_as_float(lo), __uint_as_float(hi));
}
__device__ __forceinline__ void fma2(ull& d, ull a, ull b) {
    asm("fma.rn.f32x2 %0, %1, %2, %0;" : "+l"(d) : "l"(a), "l"(b));
}

// ---------------- weight transposes (tiny, run once per launch) ----------------
__global__ void transpose_conv(const float* __restrict__ W) {
    int f = blockIdx.x;          // 0..1151
    int o = threadIdx.x;         // 0..127
    g_Wt[f * Cc + o] = W[(size_t)o * Ff + f];
}
__global__ void transpose_skip(const float* __restrict__ W) {
    int c = blockIdx.x;          // 0..127
    int o = threadIdx.x;         // 0..127
    g_Wst[c * Cc + o] = W[o * Cc + c];
}

// ---------------- pass 1: gather + P-mix + elu -> g_flat ----------------
// grid = N blocks, 128 threads; each block handles node n across all 16 batches.
__global__ __launch_bounds__(128) void build_flat(
    const float* __restrict__ x, const int* __restrict__ idx,
    const float* __restrict__ P)
{
    int n = blockIdx.x;
    int c = threadIdx.x;

    __shared__ float Ps[81];
    __shared__ int   is[9];
    if (c < 81) Ps[c] = P[(size_t)n * 81 + c];
    if (c < 9)  is[c] = idx[n * 9 + c];
    __syncthreads();

    int ir[9];
#pragma unroll
    for (int j = 0; j < 9; j++) ir[j] = is[j];

    for (int b = 0; b < Bsz; b++) {
        float nb[9];
#pragma unroll
        for (int j = 0; j < 9; j++)
            nb[j] = x[((size_t)b * Nn + ir[j]) * Cc + c];   // coalesced over c
        size_t base = ((size_t)b * Nn + n) * Ff + c;
#pragma unroll
        for (int k = 0; k < 9; k++) {
            float v = 0.f;
#pragma unroll
            for (int j = 0; j < 9; j++) v = fmaf(Ps[k * 9 + j], nb[j], v);
            v = (v > 0.f) ? v : expm1f(v);                  // elu, alpha=1
            g_flat[base + (size_t)k * Cc] = v;
        }
    }
}

// ---------------- pass 2: fused GEMM + bias + elu + skip GEMM ----------------
#define MT 128
#define NT 128
#define KT 16

// One K-chunked, double-buffered accumulation sweep: acc += A(128 x lda-sliced) @ B
__device__ __forceinline__ void run_chunks(
    const float* __restrict__ Ap, int lda,
    const float* __restrict__ Bp, int nchunks,
    float As[2][KT][MT + 4], float Bs[2][KT][NT],
    ull acc[8][4])
{
    const int tid = threadIdx.x;
    const int tx = tid & 15, ty = tid >> 4;
    const int ar = tid >> 2, ac = (tid & 3) << 2;   // A: 64 rows x 16 cols per pass
    const int bk = tid >> 5, bo = (tid & 31) << 2;  // B: 8 k x 128 o per pass

    // prologue: chunk 0 -> buffer 0
    {
        float4 p0 = *(const float4*)&Ap[(size_t)ar * lda + ac];
        float4 p1 = *(const float4*)&Ap[(size_t)(ar + 64) * lda + ac];
        As[0][ac + 0][ar] = p0.x; As[0][ac + 1][ar] = p0.y;
        As[0][ac + 2][ar] = p0.z; As[0][ac + 3][ar] = p0.w;
        As[0][ac + 0][ar + 64] = p1.x; As[0][ac + 1][ar + 64] = p1.y;
        As[0][ac + 2][ar + 64] = p1.z; As[0][ac + 3][ar + 64] = p1.w;
        float4 q0 = *(const float4*)&Bp[(size_t)bk * NT + bo];
        float4 q1 = *(const float4*)&Bp[(size_t)(bk + 8) * NT + bo];
        *(float4*)&Bs[0][bk][bo]     = q0;
        *(float4*)&Bs[0][bk + 8][bo] = q1;
    }
    __syncthreads();

    int buf = 0;
    for (int t = 0; t < nchunks; ++t) {
        float4 p0, p1, q0, q1;
        const bool pre = (t + 1 < nchunks);
        if (pre) {
            int k0 = (t + 1) * KT;
            p0 = *(const float4*)&Ap[(size_t)ar * lda + k0 + ac];
            p1 = *(const float4*)&Ap[(size_t)(ar + 64) * lda + k0 + ac];
            q0 = *(const float4*)&Bp[(size_t)(k0 + bk) * NT + bo];
            q1 = *(const float4*)&Bp[(size_t)(k0 + bk + 8) * NT + bo];
        }
#pragma unroll
        for (int kk = 0; kk < KT; ++kk) {
            float4 a0 = *(const float4*)&As[buf][kk][ty * 8];
            float4 a1 = *(const float4*)&As[buf][kk][ty * 8 + 4];
            float4 b0 = *(const float4*)&Bs[buf][kk][tx * 8];
            float4 b1 = *(const float4*)&Bs[buf][kk][tx * 8 + 4];
            ull pb0 = pack2(b0.x, b0.y), pb1 = pack2(b0.z, b0.w);
            ull pb2 = pack2(b1.x, b1.y), pb3 = pack2(b1.z, b1.w);
            float av[8] = {a0.x, a0.y, a0.z, a0.w, a1.x, a1.y, a1.z, a1.w};
#pragma unroll
            for (int i = 0; i < 8; ++i) {
                ull pa = pack2(av[i], av[i]);
                fma2(acc[i][0], pa, pb0);
                fma2(acc[i][1], pa, pb1);
                fma2(acc[i][2], pa, pb2);
                fma2(acc[i][3], pa, pb3);
            }
        }
        if (pre) {
            int nb = buf ^ 1;
            As[nb][ac + 0][ar] = p0.x; As[nb][ac + 1][ar] = p0.y;
            As[nb][ac + 2][ar] = p0.z; As[nb][ac + 3][ar] = p0.w;
            As[nb][ac + 0][ar + 64] = p1.x; As[nb][ac + 1][ar + 64] = p1.y;
            As[nb][ac + 2][ar + 64] = p1.z; As[nb][ac + 3][ar + 64] = p1.w;
            *(float4*)&Bs[nb][bk][bo]     = q0;
            *(float4*)&Bs[nb][bk + 8][bo] = q1;
        }
        __syncthreads();
        buf ^= 1;
    }
}

__global__ __launch_bounds__(256, 2) void gemm_fused(
    const float* __restrict__ X,
    const float* __restrict__ bconv,
    const float* __restrict__ bskip,
    float* __restrict__ out)
{
    __shared__ float As[2][KT][MT + 4];
    __shared__ float Bs[2][KT][NT];

    ull acc[8][4];
#pragma unroll
    for (int i = 0; i < 8; i++)
#pragma unroll
        for (int j = 0; j < 4; j++) acc[i][j] = 0ull;

    const size_t m0 = (size_t)blockIdx.x * MT;

    // conv GEMM: acc = flat @ W_conv^T   (72 chunks of K=16)
    run_chunks(g_flat + m0 * Ff, Ff, g_Wt, Ff / KT, As, Bs, acc);

    const int tid = threadIdx.x;
    const int tx = tid & 15, ty = tid >> 4;

    // acc = elu(acc + b_conv)
#pragma unroll
    for (int jj = 0; jj < 4; jj++) {
        int col = tx * 8 + jj * 2;
        float bx = bconv[col], by = bconv[col + 1];
#pragma unroll
        for (int i = 0; i < 8; i++) {
            float2 v = unpack2(acc[i][jj]);
            v.x += bx; v.y += by;
            v.x = (v.x > 0.f) ? v.x : expm1f(v.x);
            v.y = (v.y > 0.f) ? v.y : expm1f(v.y);
            acc[i][jj] = pack2(v.x, v.y);
        }
    }

    // skip GEMM: acc += x @ W_skip^T   (8 chunks of K=16)
    run_chunks(X + m0 * Cc, Cc, g_Wst, Cc / KT, As, Bs, acc);

    // out = acc + b_skip
#pragma unroll
    for (int jj = 0; jj < 4; jj++) {
        int col = tx * 8 + jj * 2;
        float bx = bskip[col], by = bskip[col + 1];
#pragma unroll
        for (int i = 0; i < 8; i++) {
            float2 v = unpack2(acc[i][jj]);
            v.x += bx; v.y += by;
            *(float2*)&out[(m0 + ty * 8 + i) * Cc + col] = v;
        }
    }
}

// ---------------- launch ----------------
extern "C" void kernel_launch(void* const* d_in, const int* in_sizes, int n_in,
                              void* d_out, int out_size)
{
    const float* x   = (const float*)d_in[0];   // (B, N, C)
    const int*   idx = (const int*)  d_in[1];   // (N, K)
    const float* P   = (const float*)d_in[2];   // (N, K, K)
    const float* Wc  = (const float*)d_in[3];   // (C_OUT, K*C)
    const float* bc  = (const float*)d_in[4];   // (C_OUT)
    const float* Ws  = (const float*)d_in[5];   // (C_OUT, C)
    const float* bs  = (const float*)d_in[6];   // (C_OUT)
    float* out = (float*)d_out;                 // (B, N, C_OUT)

    (void)in_sizes; (void)n_in; (void)out_size;

    transpose_conv<<<Ff, Cc>>>(Wc);
    transpose_skip<<<Cc, Cc>>>(Ws);
    build_flat<<<Nn, Cc>>>(x, idx, P);
    gemm_fused<<<Mm / MT, 256>>>(x, bc, bs, out);
}

// round 6
// speedup vs baseline: 1.5848x; 1.5848x over previous
#include <cuda_runtime.h>
#include <cuda_bf16.h>
#include <math.h>
#include <stdint.h>

// ---------------- problem constants ----------------
#define Bsz 16
#define Nn  16384
#define Cc  128            // C_IN == C_OUT
#define Ffull 1152         // 9 * 128
#define Mm  (Bsz * Nn)     // 262144 rows

// ---------------- static device scratch ----------------
__device__ __nv_bfloat16 g_flat_hi[(size_t)Mm * Ffull];
__device__ __nv_bfloat16 g_flat_lo[(size_t)Mm * Ffull];
__device__ __nv_bfloat16 g_x_hi[(size_t)Mm * Cc];
__device__ __nv_bfloat16 g_x_lo[(size_t)Mm * Cc];
__device__ __nv_bfloat16 g_Wc_hi[Cc * Ffull];
__device__ __nv_bfloat16 g_Wc_lo[Cc * Ffull];
__device__ __nv_bfloat16 g_Ws_hi[Cc * Cc];
__device__ __nv_bfloat16 g_Ws_lo[Cc * Cc];

// ---------------- helpers ----------------
__device__ __forceinline__ uint32_t smem_u32(const void* p) {
    uint32_t a;
    asm("{ .reg .u64 t; cvta.to.shared.u64 t, %1; cvt.u32.u64 %0, t; }" : "=r"(a) : "l"(p));
    return a;
}
__device__ __forceinline__ void cp16(uint32_t dst, const void* src) {
    asm volatile("cp.async.cg.shared.global [%0], [%1], 16;" :: "r"(dst), "l"(src) : "memory");
}
#define CP_COMMIT() asm volatile("cp.async.commit_group;" ::: "memory")
#define CP_WAIT(n)  asm volatile("cp.async.wait_group %0;" :: "n"(n) : "memory")

__device__ __forceinline__ void ldsm4(uint32_t& d0, uint32_t& d1, uint32_t& d2, uint32_t& d3, uint32_t a) {
    asm volatile("ldmatrix.sync.aligned.m8n8.x4.shared.b16 {%0,%1,%2,%3}, [%4];"
                 : "=r"(d0), "=r"(d1), "=r"(d2), "=r"(d3) : "r"(a));
}
__device__ __forceinline__ void mma16816(float* c, const uint32_t* a, const uint32_t* b) {
    asm volatile("mma.sync.aligned.m16n8k16.row.col.f32.bf16.bf16.f32 "
                 "{%0,%1,%2,%3},{%4,%5,%6,%7},{%8,%9},{%0,%1,%2,%3};"
                 : "+f"(c[0]), "+f"(c[1]), "+f"(c[2]), "+f"(c[3])
                 : "r"(a[0]), "r"(a[1]), "r"(a[2]), "r"(a[3]), "r"(b[0]), "r"(b[1]));
}

__device__ __forceinline__ void split_bf16(float v, __nv_bfloat16* hi, __nv_bfloat16* lo) {
    __nv_bfloat16 h = __float2bfloat16(v);
    *hi = h;
    *lo = __float2bfloat16(v - __bfloat162float(h));
}
__device__ __forceinline__ float elu1(float v) { return (v > 0.f) ? v : expm1f(v); }

// ---------------- pass 0: convert weights / x ----------------
__global__ void cvt_w(const float* __restrict__ Wc, const float* __restrict__ Ws) {
    int i = blockIdx.x * 256 + threadIdx.x;
    if (i < Cc * Ffull) split_bf16(Wc[i], &g_Wc_hi[i], &g_Wc_lo[i]);
    if (i < Cc * Cc)    split_bf16(Ws[i], &g_Ws_hi[i], &g_Ws_lo[i]);
}
__global__ void cvt_x(const float* __restrict__ x) {
    size_t i = (size_t)blockIdx.x * 256 + threadIdx.x;
    if (i < (size_t)Mm * Cc) split_bf16(x[i], &g_x_hi[i], &g_x_lo[i]);
}

// ---------------- pass 1: gather + P-mix + elu -> g_flat hi/lo ----------------
__global__ __launch_bounds__(128) void build_flat(
    const float* __restrict__ x, const int* __restrict__ idx, const float* __restrict__ P)
{
    int n = blockIdx.x;
    int c = threadIdx.x;
    __shared__ float Ps[81];
    __shared__ int   is[9];
    if (c < 81) Ps[c] = P[(size_t)n * 81 + c];
    if (c < 9)  is[c] = idx[n * 9 + c];
    __syncthreads();
    int ir[9];
#pragma unroll
    for (int j = 0; j < 9; j++) ir[j] = is[j];

    for (int b = 0; b < Bsz; b++) {
        float nb[9];
#pragma unroll
        for (int j = 0; j < 9; j++)
            nb[j] = x[((size_t)b * Nn + ir[j]) * Cc + c];
        size_t base = ((size_t)b * Nn + n) * Ffull + c;
#pragma unroll
        for (int k = 0; k < 9; k++) {
            float v = 0.f;
#pragma unroll
            for (int j = 0; j < 9; j++) v = fmaf(Ps[k * 9 + j], nb[j], v);
            v = elu1(v);
            __nv_bfloat16 h, l;
            split_bf16(v, &h, &l);
            g_flat_hi[base + (size_t)k * Cc] = h;
            g_flat_lo[base + (size_t)k * Cc] = l;
        }
    }
}

// ---------------- pass 2: mma.sync split-bf16 GEMM, fused epilogue ----------------
// 20 K-chunks of 64: 0..17 conv (g_flat @ Wc^T), then reg-level bias+elu,
// then 18..19 skip (x @ Ws^T) accumulated on top. out = that + b_skip.
#define NCH     20
#define TILE_B  16384                 // 128 rows x 128 bytes (64 bf16)
#define STAGE_B (4 * TILE_B)          // Ah, Al, Bh, Bl
#define NSTAGE  3
#define SMEM_B  (NSTAGE * STAGE_B)    // 196608

// swizzled smem offset for (row r, 16B-granule g)
#define SWO(r, g) ((uint32_t)(r) * 128u + (uint32_t)(((g) ^ ((r) & 7)) << 4))

__global__ __launch_bounds__(256, 1) void gemm_mma(
    const float* __restrict__ bconv, const float* __restrict__ bskip,
    float* __restrict__ out)
{
    extern __shared__ char smem[];
    const uint32_t sb = smem_u32(smem);
    const int tid = threadIdx.x;
    const int lane = tid & 31, wid = tid >> 5;
    const int warpM = wid >> 2, warpN = wid & 3;      // 2 x 4 warp grid
    const size_t mrow0 = (size_t)blockIdx.x * 128;

    // ---- async tile loader: chunk t -> stage s ----
    auto issue = [&](int t, int s) {
        const __nv_bfloat16 *Ah, *Al, *Bh, *Bl;
        size_t astr; int bstr, off;
        if (t < 18) {
            Ah = g_flat_hi; Al = g_flat_lo; Bh = g_Wc_hi; Bl = g_Wc_lo;
            astr = Ffull; bstr = Ffull; off = t * 64;
        } else {
            Ah = g_x_hi; Al = g_x_lo; Bh = g_Ws_hi; Bl = g_Ws_lo;
            astr = Cc; bstr = Cc; off = (t - 18) * 64;
        }
        const uint32_t st = sb + (uint32_t)s * STAGE_B;
#pragma unroll
        for (int i = 0; i < 4; i++) {
            int idx2 = i * 256 + tid;
            int r = idx2 >> 3, g = idx2 & 7;
            uint32_t d = SWO(r, g);
            size_t ao = (mrow0 + r) * astr + off + g * 8;
            size_t bo = (size_t)r * bstr + off + g * 8;
            cp16(st + 0 * TILE_B + d, Ah + ao);
            cp16(st + 1 * TILE_B + d, Al + ao);
            cp16(st + 2 * TILE_B + d, Bh + bo);
            cp16(st + 3 * TILE_B + d, Bl + bo);
        }
        CP_COMMIT();
    };

    float acc[4][4][4];
#pragma unroll
    for (int mi = 0; mi < 4; mi++)
#pragma unroll
        for (int ni = 0; ni < 4; ni++)
#pragma unroll
            for (int j = 0; j < 4; j++) acc[mi][ni][j] = 0.f;

    issue(0, 0); issue(1, 1); issue(2, 2);

    const int lr = lane & 15;          // ldmatrix row within 16-row group
    const int lg = lane >> 4;          // ldmatrix granule half

    for (int t = 0; t < NCH; t++) {
        if (t < NCH - 2)      CP_WAIT(2);
        else if (t == NCH - 2) CP_WAIT(1);
        else                   CP_WAIT(0);
        __syncthreads();

        const uint32_t st = sb + (uint32_t)(t % NSTAGE) * STAGE_B;
#pragma unroll
        for (int kk = 0; kk < 4; kk++) {
            const int g = kk * 2 + lg;
            uint32_t Ahf[4][4], Alf[4][4], Bhf[4][2], Blf[4][2];
#pragma unroll
            for (int mi = 0; mi < 4; mi++) {
                int r = warpM * 64 + mi * 16 + lr;
                uint32_t o = SWO(r, g);
                ldsm4(Ahf[mi][0], Ahf[mi][1], Ahf[mi][2], Ahf[mi][3], st + 0 * TILE_B + o);
                ldsm4(Alf[mi][0], Alf[mi][1], Alf[mi][2], Alf[mi][3], st + 1 * TILE_B + o);
            }
#pragma unroll
            for (int np = 0; np < 2; np++) {
                int r = warpN * 32 + np * 16 + lr;
                uint32_t o = SWO(r, g);
                uint32_t h0, h1, h2, h3, l0, l1, l2, l3;
                ldsm4(h0, h1, h2, h3, st + 2 * TILE_B + o);
                ldsm4(l0, l1, l2, l3, st + 3 * TILE_B + o);
                // matrices: m0=(n0..7,k0..7) m1=(n8..15,k0..7) m2=(n0..7,k8..15) m3=(n8..15,k8..15)
                Bhf[np * 2 + 0][0] = h0; Bhf[np * 2 + 0][1] = h2;
                Bhf[np * 2 + 1][0] = h1; Bhf[np * 2 + 1][1] = h3;
                Blf[np * 2 + 0][0] = l0; Blf[np * 2 + 0][1] = l2;
                Blf[np * 2 + 1][0] = l1; Blf[np * 2 + 1][1] = l3;
            }
#pragma unroll
            for (int mi = 0; mi < 4; mi++)
#pragma unroll
                for (int ni = 0; ni < 4; ni++) {
                    mma16816(acc[mi][ni], Ahf[mi], Bhf[ni]);
                    mma16816(acc[mi][ni], Alf[mi], Bhf[ni]);
                    mma16816(acc[mi][ni], Ahf[mi], Blf[ni]);
                }
        }

        if (t == 17) {
            // conv done: acc = elu(acc + b_conv), then skip chunks accumulate on top
#pragma unroll
            for (int ni = 0; ni < 4; ni++) {
                int col = warpN * 32 + ni * 8 + 2 * (lane & 3);
                float b0 = __ldg(bconv + col), b1 = __ldg(bconv + col + 1);
#pragma unroll
                for (int mi = 0; mi < 4; mi++) {
                    acc[mi][ni][0] = elu1(acc[mi][ni][0] + b0);
                    acc[mi][ni][1] = elu1(acc[mi][ni][1] + b1);
                    acc[mi][ni][2] = elu1(acc[mi][ni][2] + b0);
                    acc[mi][ni][3] = elu1(acc[mi][ni][3] + b1);
                }
            }
        }

        __syncthreads();
        if (t + NSTAGE < NCH) issue(t + NSTAGE, (t + NSTAGE) % NSTAGE);
    }

    // ---- epilogue: out = acc + b_skip ----
#pragma unroll
    for (int ni = 0; ni < 4; ni++) {
        int col = warpN * 32 + ni * 8 + 2 * (lane & 3);
        float b0 = __ldg(bskip + col), b1 = __ldg(bskip + col + 1);
#pragma unroll
        for (int mi = 0; mi < 4; mi++) {
            size_t r0 = mrow0 + warpM * 64 + mi * 16 + (lane >> 2);
            float2 v0 = make_float2(acc[mi][ni][0] + b0, acc[mi][ni][1] + b1);
            float2 v1 = make_float2(acc[mi][ni][2] + b0, acc[mi][ni][3] + b1);
            *(float2*)&out[r0 * Cc + col]       = v0;
            *(float2*)&out[(r0 + 8) * Cc + col] = v1;
        }
    }
}

// ---------------- launch ----------------
extern "C" void kernel_launch(void* const* d_in, const int* in_sizes, int n_in,
                              void* d_out, int out_size)
{
    const float* x   = (const float*)d_in[0];
    const int*   idx = (const int*)  d_in[1];
    const float* P   = (const float*)d_in[2];
    const float* Wc  = (const float*)d_in[3];
    const float* bc  = (const float*)d_in[4];
    const float* Ws  = (const float*)d_in[5];
    const float* bs  = (const float*)d_in[6];
    float* out = (float*)d_out;
    (void)in_sizes; (void)n_in; (void)out_size;

    cudaFuncSetAttribute(gemm_mma, cudaFuncAttributeMaxDynamicSharedMemorySize, SMEM_B);

    cvt_w<<<(Cc * Ffull + 255) / 256, 256>>>(Wc, Ws);
    cvt_x<<<(int)(((size_t)Mm * Cc + 255) / 256), 256>>>(x);
    build_flat<<<Nn, 128>>>(x, idx, P);
    gemm_mma<<<Mm / 128, 256, SMEM_B>>>(bc, bs, out);
}

// round 7
// speedup vs baseline: 2.5498x; 1.6090x over previous
#include <cuda_runtime.h>
#include <cuda_bf16.h>
#include <math.h>
#include <stdint.h>

// ---------------- problem constants ----------------
#define Bsz 16
#define Nn  16384
#define Cc  128            // C_IN == C_OUT
#define Ffull 1152         // 9 * 128
#define Mm  (Bsz * Nn)     // 262144 rows

// ---------------- static device scratch ----------------
__device__ __nv_bfloat16 g_flat_hi[(size_t)Mm * Ffull];
__device__ __nv_bfloat16 g_flat_lo[(size_t)Mm * Ffull];
__device__ __nv_bfloat16 g_x_hi[(size_t)Mm * Cc];
__device__ __nv_bfloat16 g_x_lo[(size_t)Mm * Cc];
__device__ __nv_bfloat16 g_Wc_hi[Cc * Ffull];
__device__ __nv_bfloat16 g_Wc_lo[Cc * Ffull];
__device__ __nv_bfloat16 g_Ws_hi[Cc * Cc];
__device__ __nv_bfloat16 g_Ws_lo[Cc * Cc];

// ---------------- helpers ----------------
__device__ __forceinline__ uint32_t smem_u32(const void* p) {
    uint32_t a;
    asm("{ .reg .u64 t; cvta.to.shared.u64 t, %1; cvt.u32.u64 %0, t; }" : "=r"(a) : "l"(p));
    return a;
}
__device__ __forceinline__ void cp16(uint32_t dst, const void* src) {
    asm volatile("cp.async.cg.shared.global [%0], [%1], 16;" :: "r"(dst), "l"(src) : "memory");
}
#define CP_COMMIT() asm volatile("cp.async.commit_group;" ::: "memory")
#define CP_WAIT(n)  asm volatile("cp.async.wait_group %0;" :: "n"(n) : "memory")

__device__ __forceinline__ void ldsm4(uint32_t& d0, uint32_t& d1, uint32_t& d2, uint32_t& d3, uint32_t a) {
    asm volatile("ldmatrix.sync.aligned.m8n8.x4.shared.b16 {%0,%1,%2,%3}, [%4];"
                 : "=r"(d0), "=r"(d1), "=r"(d2), "=r"(d3) : "r"(a));
}
__device__ __forceinline__ void mma16816(float* c, const uint32_t* a, const uint32_t* b) {
    asm volatile("mma.sync.aligned.m16n8k16.row.col.f32.bf16.bf16.f32 "
                 "{%0,%1,%2,%3},{%4,%5,%6,%7},{%8,%9},{%0,%1,%2,%3};"
                 : "+f"(c[0]), "+f"(c[1]), "+f"(c[2]), "+f"(c[3])
                 : "r"(a[0]), "r"(a[1]), "r"(a[2]), "r"(a[3]), "r"(b[0]), "r"(b[1]));
}

__device__ __forceinline__ void split_bf16(float v, __nv_bfloat16* hi, __nv_bfloat16* lo) {
    __nv_bfloat16 h = __float2bfloat16(v);
    *hi = h;
    *lo = __float2bfloat16(v - __bfloat162float(h));
}
__device__ __forceinline__ float elu1(float v) { return (v > 0.f) ? v : expm1f(v); }

// ---------------- pass 0: convert weights / x ----------------
__global__ void cvt_w(const float* __restrict__ Wc, const float* __restrict__ Ws) {
    int i = blockIdx.x * 256 + threadIdx.x;
    if (i < Cc * Ffull) split_bf16(Wc[i], &g_Wc_hi[i], &g_Wc_lo[i]);
    if (i < Cc * Cc)    split_bf16(Ws[i], &g_Ws_hi[i], &g_Ws_lo[i]);
}
__global__ __launch_bounds__(256) void cvt_x(const float* __restrict__ x) {
    size_t i4 = (size_t)blockIdx.x * 256 + threadIdx.x;   // index over float4s
    if (i4 >= (size_t)Mm * Cc / 4) return;
    float4 v = *(const float4*)(x + i4 * 4);
    __nv_bfloat16 h0, l0, h1, l1, h2, l2, h3, l3;
    split_bf16(v.x, &h0, &l0); split_bf16(v.y, &h1, &l1);
    split_bf16(v.z, &h2, &l2); split_bf16(v.w, &h3, &l3);
    ((__nv_bfloat162*)g_x_hi)[i4 * 2]     = __nv_bfloat162(h0, h1);
    ((__nv_bfloat162*)g_x_hi)[i4 * 2 + 1] = __nv_bfloat162(h2, h3);
    ((__nv_bfloat162*)g_x_lo)[i4 * 2]     = __nv_bfloat162(l0, l1);
    ((__nv_bfloat162*)g_x_lo)[i4 * 2 + 1] = __nv_bfloat162(l2, l3);
}

// ---------------- pass 1: gather + P-mix + elu -> g_flat hi/lo ----------------
// 128 threads: c2 = tid&63 -> channel pair (2c2, 2c2+1); tid>>6 -> batch half.
__global__ __launch_bounds__(128) void build_flat(
    const float* __restrict__ x, const int* __restrict__ idx, const float* __restrict__ P)
{
    const int n = blockIdx.x;
    const int tid = threadIdx.x;
    const int c2 = (tid & 63) * 2;
    const int b0 = (tid >> 6) * 8;

    __shared__ float Ps[81];
    __shared__ int   is[9];
    if (tid < 81) Ps[tid] = P[(size_t)n * 81 + tid];
    if (tid < 9)  is[tid] = idx[n * 9 + tid];
    __syncthreads();
    int ir[9];
#pragma unroll
    for (int j = 0; j < 9; j++) ir[j] = is[j];

    for (int bb = 0; bb < 8; bb++) {
        const int b = b0 + bb;
        float2 nb[9];
#pragma unroll
        for (int j = 0; j < 9; j++)
            nb[j] = *(const float2*)&x[((size_t)b * Nn + ir[j]) * Cc + c2];
        const size_t base = ((size_t)b * Nn + n) * Ffull + c2;
#pragma unroll
        for (int k = 0; k < 9; k++) {
            float v0 = 0.f, v1 = 0.f;
#pragma unroll
            for (int j = 0; j < 9; j++) {
                float p = Ps[k * 9 + j];
                v0 = fmaf(p, nb[j].x, v0);
                v1 = fmaf(p, nb[j].y, v1);
            }
            v0 = elu1(v0); v1 = elu1(v1);
            __nv_bfloat16 h0, l0, h1, l1;
            split_bf16(v0, &h0, &l0);
            split_bf16(v1, &h1, &l1);
            size_t o = base + (size_t)k * Cc;
            *(__nv_bfloat162*)(g_flat_hi + o) = __nv_bfloat162(h0, h1);
            *(__nv_bfloat162*)(g_flat_lo + o) = __nv_bfloat162(l0, l1);
        }
    }
}

// ---------------- pass 2: mma.sync split-bf16 GEMM, fused epilogue ----------------
// K-chunks of 32: 36 conv chunks (g_flat @ Wc^T), reg-level bias+elu, then 4
// skip chunks (x @ Ws^T) on top. 3-stage cp.async, 96KB smem -> 2 CTAs/SM.
#define NCH     40
#define NCONV   36
#define TILE_B  8192                  // 128 rows x 64 bytes (32 bf16)
#define STAGE_B (4 * TILE_B)          // Ah, Al, Bh, Bl = 32KB
#define NSTAGE  3
#define SMEM_B  (NSTAGE * STAGE_B)    // 98304

// swizzled offset for (row r, 16B-granule g in 0..3), 64B rows
#define SWO(r, g) ((uint32_t)(r) * 64u + (uint32_t)((((g) ^ (((r) >> 1) & 3))) << 4))

__global__ __launch_bounds__(256, 2) void gemm_mma(
    const float* __restrict__ bconv, const float* __restrict__ bskip,
    float* __restrict__ out)
{
    extern __shared__ char smem[];
    const uint32_t sb = smem_u32(smem);
    const int tid = threadIdx.x;
    const int lane = tid & 31, wid = tid >> 5;
    const int warpM = wid >> 2, warpN = wid & 3;      // 2 x 4 warp grid
    const size_t mrow0 = (size_t)blockIdx.x * 128;

    // ---- async tile loader: chunk t -> stage s ----
    auto issue = [&](int t, int s) {
        const __nv_bfloat16 *Ah, *Al, *Bh, *Bl;
        size_t astr; int bstr, off;
        if (t < NCONV) {
            Ah = g_flat_hi; Al = g_flat_lo; Bh = g_Wc_hi; Bl = g_Wc_lo;
            astr = Ffull; bstr = Ffull; off = t * 32;
        } else {
            Ah = g_x_hi; Al = g_x_lo; Bh = g_Ws_hi; Bl = g_Ws_lo;
            astr = Cc; bstr = Cc; off = (t - NCONV) * 32;
        }
        const uint32_t st = sb + (uint32_t)s * STAGE_B;
#pragma unroll
        for (int i = 0; i < 2; i++) {
            int idx2 = i * 256 + tid;          // 512 granules per tile
            int r = idx2 >> 2, g = idx2 & 3;
            uint32_t d = SWO(r, g);
            size_t ao = (mrow0 + r) * astr + off + g * 8;
            size_t bo = (size_t)r * bstr + off + g * 8;
            cp16(st + 0 * TILE_B + d, Ah + ao);
            cp16(st + 1 * TILE_B + d, Al + ao);
            cp16(st + 2 * TILE_B + d, Bh + bo);
            cp16(st + 3 * TILE_B + d, Bl + bo);
        }
        CP_COMMIT();
    };

    float acc[4][4][4];
#pragma unroll
    for (int mi = 0; mi < 4; mi++)
#pragma unroll
        for (int ni = 0; ni < 4; ni++)
#pragma unroll
            for (int j = 0; j < 4; j++) acc[mi][ni][j] = 0.f;

    issue(0, 0); issue(1, 1); issue(2, 2);

    const int lr = lane & 15;          // ldmatrix row within 16-row group
    const int lg = lane >> 4;          // granule half

    for (int t = 0; t < NCH; t++) {
        if (t < NCH - 2)       CP_WAIT(2);
        else if (t == NCH - 2) CP_WAIT(1);
        else                   CP_WAIT(0);
        __syncthreads();

        const uint32_t st = sb + (uint32_t)(t % NSTAGE) * STAGE_B;
#pragma unroll
        for (int kk = 0; kk < 2; kk++) {
            const int g = kk * 2 + lg;
            uint32_t Ahf[4][4], Alf[4][4], Bhf[4][2], Blf[4][2];
#pragma unroll
            for (int mi = 0; mi < 4; mi++) {
                int r = warpM * 64 + mi * 16 + lr;
                uint32_t o = SWO(r, g);
                ldsm4(Ahf[mi][0], Ahf[mi][1], Ahf[mi][2], Ahf[mi][3], st + 0 * TILE_B + o);
                ldsm4(Alf[mi][0], Alf[mi][1], Alf[mi][2], Alf[mi][3], st + 1 * TILE_B + o);
            }
#pragma unroll
            for (int np = 0; np < 2; np++) {
                int r = warpN * 32 + np * 16 + lr;
                uint32_t o = SWO(r, g);
                uint32_t h0, h1, h2, h3, l0, l1, l2, l3;
                ldsm4(h0, h1, h2, h3, st + 2 * TILE_B + o);
                ldsm4(l0, l1, l2, l3, st + 3 * TILE_B + o);
                Bhf[np * 2 + 0][0] = h0; Bhf[np * 2 + 0][1] = h2;
                Bhf[np * 2 + 1][0] = h1; Bhf[np * 2 + 1][1] = h3;
                Blf[np * 2 + 0][0] = l0; Blf[np * 2 + 0][1] = l2;
                Blf[np * 2 + 1][0] = l1; Blf[np * 2 + 1][1] = l3;
            }
#pragma unroll
            for (int mi = 0; mi < 4; mi++)
#pragma unroll
                for (int ni = 0; ni < 4; ni++) {
                    mma16816(acc[mi][ni], Ahf[mi], Bhf[ni]);
                    mma16816(acc[mi][ni], Alf[mi], Bhf[ni]);
                    mma16816(acc[mi][ni], Ahf[mi], Blf[ni]);
                }
        }

        if (t == NCONV - 1) {
            // conv done: acc = elu(acc + b_conv); skip chunks then accumulate on top
#pragma unroll
            for (int ni = 0; ni < 4; ni++) {
                int col = warpN * 32 + ni * 8 + 2 * (lane & 3);
                float b0 = __ldg(bconv + col), b1 = __ldg(bconv + col + 1);
#pragma unroll
                for (int mi = 0; mi < 4; mi++) {
                    acc[mi][ni][0] = elu1(acc[mi][ni][0] + b0);
                    acc[mi][ni][1] = elu1(acc[mi][ni][1] + b1);
                    acc[mi][ni][2] = elu1(acc[mi][ni][2] + b0);
                    acc[mi][ni][3] = elu1(acc[mi][ni][3] + b1);
                }
            }
        }

        __syncthreads();
        if (t + NSTAGE < NCH) issue(t + NSTAGE, (t + NSTAGE) % NSTAGE);
    }

    // ---- epilogue: out = acc + b_skip ----
#pragma unroll
    for (int ni = 0; ni < 4; ni++) {
        int col = warpN * 32 + ni * 8 + 2 * (lane & 3);
        float b0 = __ldg(bskip + col), b1 = __ldg(bskip + col + 1);
#pragma unroll
        for (int mi = 0; mi < 4; mi++) {
            size_t r0 = mrow0 + warpM * 64 + mi * 16 + (lane >> 2);
            float2 v0 = make_float2(acc[mi][ni][0] + b0, acc[mi][ni][1] + b1);
            float2 v1 = make_float2(acc[mi][ni][2] + b0, acc[mi][ni][3] + b1);
            *(float2*)&out[r0 * Cc + col]       = v0;
            *(float2*)&out[(r0 + 8) * Cc + col] = v1;
        }
    }
}

// ---------------- launch ----------------
extern "C" void kernel_launch(void* const* d_in, const int* in_sizes, int n_in,
                              void* d_out, int out_size)
{
    const float* x   = (const float*)d_in[0];
    const int*   idx = (const int*)  d_in[1];
    const float* P   = (const float*)d_in[2];
    const float* Wc  = (const float*)d_in[3];
    const float* bc  = (const float*)d_in[4];
    const float* Ws  = (const float*)d_in[5];
    const float* bs  = (const float*)d_in[6];
    float* out = (float*)d_out;
    (void)in_sizes; (void)n_in; (void)out_size;

    cudaFuncSetAttribute(gemm_mma, cudaFuncAttributeMaxDynamicSharedMemorySize, SMEM_B);

    cvt_w<<<(Cc * Ffull + 255) / 256, 256>>>(Wc, Ws);
    cvt_x<<<(int)(((size_t)Mm * Cc / 4 + 255) / 256), 256>>>(x);
    build_flat<<<Nn, 128>>>(x, idx, P);
    gemm_mma<<<Mm / 128, 256, SMEM_B>>>(bc, bs, out);
}

// round 8
// speedup vs baseline: 2.7153x; 1.0649x over previous
#include <cuda_runtime.h>
#include <cuda_bf16.h>
#include <math.h>
#include <stdint.h>

// ---------------- problem constants ----------------
#define Bsz 16
#define Nn  16384
#define Cc  128            // C_IN == C_OUT
#define Ffull 1152         // 9 * 128
#define Mm  (Bsz * Nn)     // 262144 rows

// ---------------- static device scratch ----------------
__device__ __nv_bfloat16 g_flat_hi[(size_t)Mm * Ffull];
__device__ __nv_bfloat16 g_flat_lo[(size_t)Mm * Ffull];
__device__ __nv_bfloat16 g_x_hi[(size_t)Mm * Cc];
__device__ __nv_bfloat16 g_x_lo[(size_t)Mm * Cc];
__device__ __nv_bfloat16 g_Wc_hi[Cc * Ffull];
__device__ __nv_bfloat16 g_Wc_lo[Cc * Ffull];
__device__ __nv_bfloat16 g_Ws_hi[Cc * Cc];
__device__ __nv_bfloat16 g_Ws_lo[Cc * Cc];

// ---------------- helpers ----------------
__device__ __forceinline__ uint32_t smem_u32(const void* p) {
    uint32_t a;
    asm("{ .reg .u64 t; cvta.to.shared.u64 t, %1; cvt.u32.u64 %0, t; }" : "=r"(a) : "l"(p));
    return a;
}
__device__ __forceinline__ void cp16(uint32_t dst, const void* src) {
    asm volatile("cp.async.cg.shared.global [%0], [%1], 16;" :: "r"(dst), "l"(src) : "memory");
}
#define CP_COMMIT() asm volatile("cp.async.commit_group;" ::: "memory")
#define CP_WAIT(n)  asm volatile("cp.async.wait_group %0;" :: "n"(n) : "memory")

__device__ __forceinline__ void ldsm4(uint32_t& d0, uint32_t& d1, uint32_t& d2, uint32_t& d3, uint32_t a) {
    asm volatile("ldmatrix.sync.aligned.m8n8.x4.shared.b16 {%0,%1,%2,%3}, [%4];"
                 : "=r"(d0), "=r"(d1), "=r"(d2), "=r"(d3) : "r"(a));
}
__device__ __forceinline__ void mma16816(float* c, const uint32_t* a, const uint32_t* b) {
    asm volatile("mma.sync.aligned.m16n8k16.row.col.f32.bf16.bf16.f32 "
                 "{%0,%1,%2,%3},{%4,%5,%6,%7},{%8,%9},{%0,%1,%2,%3};"
                 : "+f"(c[0]), "+f"(c[1]), "+f"(c[2]), "+f"(c[3])
                 : "r"(a[0]), "r"(a[1]), "r"(a[2]), "r"(a[3]), "r"(b[0]), "r"(b[1]));
}

__device__ __forceinline__ void split_bf16(float v, __nv_bfloat16* hi, __nv_bfloat16* lo) {
    __nv_bfloat16 h = __float2bfloat16(v);
    *hi = h;
    *lo = __float2bfloat16(v - __bfloat162float(h));
}
__device__ __forceinline__ float elu1(float v) { return (v > 0.f) ? v : expm1f(v); }
__device__ __forceinline__ uint32_t pack_bf2(__nv_bfloat16 a, __nv_bfloat16 b) {
    __nv_bfloat162 t(a, b);
    return *(uint32_t*)&t;
}

// ---------------- pass 0: convert weights / x ----------------
__global__ void cvt_w(const float* __restrict__ Wc, const float* __restrict__ Ws) {
    int i = blockIdx.x * 256 + threadIdx.x;
    if (i < Cc * Ffull) split_bf16(Wc[i], &g_Wc_hi[i], &g_Wc_lo[i]);
    if (i < Cc * Cc)    split_bf16(Ws[i], &g_Ws_hi[i], &g_Ws_lo[i]);
}
__global__ __launch_bounds__(256) void cvt_x(const float* __restrict__ x) {
    size_t i4 = (size_t)blockIdx.x * 256 + threadIdx.x;   // index over float4s
    if (i4 >= (size_t)Mm * Cc / 4) return;
    float4 v = *(const float4*)(x + i4 * 4);
    __nv_bfloat16 h0, l0, h1, l1, h2, l2, h3, l3;
    split_bf16(v.x, &h0, &l0); split_bf16(v.y, &h1, &l1);
    split_bf16(v.z, &h2, &l2); split_bf16(v.w, &h3, &l3);
    uint2 hv, lv;
    hv.x = pack_bf2(h0, h1); hv.y = pack_bf2(h2, h3);
    lv.x = pack_bf2(l0, l1); lv.y = pack_bf2(l2, l3);
    *(uint2*)(g_x_hi + i4 * 4) = hv;
    *(uint2*)(g_x_lo + i4 * 4) = lv;
}

// ---------------- pass 1: gather + P-mix + elu -> g_flat hi/lo ----------------
// 128 threads / node: c4 = (tid&31)*4 channel quad; tid>>5 -> batch quad.
__global__ __launch_bounds__(128) void build_flat(
    const float* __restrict__ x, const int* __restrict__ idx, const float* __restrict__ P)
{
    const int n = blockIdx.x;
    const int tid = threadIdx.x;
    const int c4 = (tid & 31) * 4;
    const int b0 = (tid >> 5) * 4;

    __shared__ float Ps[81];
    __shared__ int   is[9];
    if (tid < 81) Ps[tid] = P[(size_t)n * 81 + tid];
    if (tid < 9)  is[tid] = idx[n * 9 + tid];
    __syncthreads();
    int ir[9];
#pragma unroll
    for (int j = 0; j < 9; j++) ir[j] = is[j];

    for (int bb = 0; bb < 4; bb++) {
        const int b = b0 + bb;
        float4 nb[9];
#pragma unroll
        for (int j = 0; j < 9; j++)
            nb[j] = *(const float4*)&x[((size_t)b * Nn + ir[j]) * Cc + c4];
        const size_t base = ((size_t)b * Nn + n) * Ffull + c4;
#pragma unroll
        for (int k = 0; k < 9; k++) {
            float v0 = 0.f, v1 = 0.f, v2 = 0.f, v3 = 0.f;
#pragma unroll
            for (int j = 0; j < 9; j++) {
                float p = Ps[k * 9 + j];
                v0 = fmaf(p, nb[j].x, v0);
                v1 = fmaf(p, nb[j].y, v1);
                v2 = fmaf(p, nb[j].z, v2);
                v3 = fmaf(p, nb[j].w, v3);
            }
            v0 = elu1(v0); v1 = elu1(v1); v2 = elu1(v2); v3 = elu1(v3);
            __nv_bfloat16 h0, l0, h1, l1, h2, l2, h3, l3;
            split_bf16(v0, &h0, &l0); split_bf16(v1, &h1, &l1);
            split_bf16(v2, &h2, &l2); split_bf16(v3, &h3, &l3);
            uint2 hv, lv;
            hv.x = pack_bf2(h0, h1); hv.y = pack_bf2(h2, h3);
            lv.x = pack_bf2(l0, l1); lv.y = pack_bf2(l2, l3);
            size_t o = base + (size_t)k * Cc;
            *(uint2*)(g_flat_hi + o) = hv;
            *(uint2*)(g_flat_lo + o) = lv;
        }
    }
}

// ---------------- pass 2: mma.sync split-bf16 GEMM, fused epilogue ----------------
// K-chunks of 32: 36 conv chunks (g_flat @ Wc^T), reg-level bias+elu, then 4
// skip chunks (x @ Ws^T) on top. 3-stage cp.async, single-sync multistage,
// 96KB smem -> 2 CTAs/SM.
#define NCH     40
#define NCONV   36
#define TILE_B  8192                  // 128 rows x 64 bytes (32 bf16)
#define STAGE_B (4 * TILE_B)          // Ah, Al, Bh, Bl = 32KB
#define NSTAGE  3
#define SMEM_B  (NSTAGE * STAGE_B)    // 98304

// swizzled offset for (row r, 16B-granule g in 0..3), 64B rows
#define SWO(r, g) ((uint32_t)(r) * 64u + (uint32_t)((((g) ^ (((r) >> 1) & 3))) << 4))

__global__ __launch_bounds__(256, 2) void gemm_mma(
    const float* __restrict__ bconv, const float* __restrict__ bskip,
    float* __restrict__ out)
{
    extern __shared__ char smem[];
    const uint32_t sb = smem_u32(smem);
    const int tid = threadIdx.x;
    const int lane = tid & 31, wid = tid >> 5;
    const int warpM = wid >> 2, warpN = wid & 3;      // 2 x 4 warp grid
    const size_t mrow0 = (size_t)blockIdx.x * 128;

    // ---- hoisted loader geometry (loop-invariant) ----
    const int lrw = tid >> 2, lgw = tid & 3;          // 512 granules per tile, 2 waves
    uint32_t sdst[2];                                 // swizzled dst offsets (i=0,1)
    const __nv_bfloat16* aC[2]; const __nv_bfloat16* bC[2];   // conv src base ptrs
    const __nv_bfloat16* aS[2]; const __nv_bfloat16* bS[2];   // skip src base ptrs
#pragma unroll
    for (int i = 0; i < 2; i++) {
        int r = i * 64 + lrw;
        sdst[i] = SWO(r, lgw);
        aC[i] = g_flat_hi + (mrow0 + r) * (size_t)Ffull + lgw * 8;
        bC[i] = g_Wc_hi   + (size_t)r * Ffull          + lgw * 8;
        aS[i] = g_x_hi    + (mrow0 + r) * (size_t)Cc   + lgw * 8;
        bS[i] = g_Ws_hi   + (size_t)r * Cc             + lgw * 8;
    }
    const size_t dAlo = g_flat_lo - g_flat_hi;        // element offsets between arrays
    const size_t dBlo = g_Wc_lo - g_Wc_hi;
    const size_t dAloS = g_x_lo - g_x_hi;
    const size_t dBloS = g_Ws_lo - g_Ws_hi;

    auto issue = [&](int t, int s) {
        const uint32_t st = sb + (uint32_t)s * STAGE_B;
        if (t < NCONV) {
            const int off = t * 32;
#pragma unroll
            for (int i = 0; i < 2; i++) {
                uint32_t d = st + sdst[i];
                cp16(d + 0 * TILE_B, aC[i] + off);
                cp16(d + 1 * TILE_B, aC[i] + off + dAlo);
                cp16(d + 2 * TILE_B, bC[i] + off);
                cp16(d + 3 * TILE_B, bC[i] + off + dBlo);
            }
        } else {
            const int off = (t - NCONV) * 32;
#pragma unroll
            for (int i = 0; i < 2; i++) {
                uint32_t d = st + sdst[i];
                cp16(d + 0 * TILE_B, aS[i] + off);
                cp16(d + 1 * TILE_B, aS[i] + off + dAloS);
                cp16(d + 2 * TILE_B, bS[i] + off);
                cp16(d + 3 * TILE_B, bS[i] + off + dBloS);
            }
        }
        CP_COMMIT();
    };

    // ---- hoisted ldmatrix offsets (within a stage) ----
    const int lr = lane & 15, lg = lane >> 4;
    uint32_t aoff[4][2], boff[2][2];
#pragma unroll
    for (int kk = 0; kk < 2; kk++) {
        const int g = kk * 2 + lg;
#pragma unroll
        for (int mi = 0; mi < 4; mi++) aoff[mi][kk] = SWO(warpM * 64 + mi * 16 + lr, g);
#pragma unroll
        for (int np = 0; np < 2; np++) boff[np][kk] = SWO(warpN * 32 + np * 16 + lr, g);
    }

    float acc[4][4][4];
#pragma unroll
    for (int mi = 0; mi < 4; mi++)
#pragma unroll
        for (int ni = 0; ni < 4; ni++)
#pragma unroll
            for (int j = 0; j < 4; j++) acc[mi][ni][j] = 0.f;

    issue(0, 0); issue(1, 1);

    for (int t = 0; t < NCH; t++) {
        if (t + 1 < NCH) CP_WAIT(1); else CP_WAIT(0);
        __syncthreads();
        if (t + 2 < NCH) issue(t + 2, (t + 2) % NSTAGE);   // overlaps compute below

        const uint32_t st = sb + (uint32_t)(t % NSTAGE) * STAGE_B;
#pragma unroll
        for (int kk = 0; kk < 2; kk++) {
            uint32_t Ahf[4][4], Alf[4][4], Bhf[4][2], Blf[4][2];
#pragma unroll
            for (int mi = 0; mi < 4; mi++) {
                uint32_t o = st + aoff[mi][kk];
                ldsm4(Ahf[mi][0], Ahf[mi][1], Ahf[mi][2], Ahf[mi][3], o);
                ldsm4(Alf[mi][0], Alf[mi][1], Alf[mi][2], Alf[mi][3], o + TILE_B);
            }
#pragma unroll
            for (int np = 0; np < 2; np++) {
                uint32_t o = st + boff[np][kk];
                uint32_t h0, h1, h2, h3, l0, l1, l2, l3;
                ldsm4(h0, h1, h2, h3, o + 2 * TILE_B);
                ldsm4(l0, l1, l2, l3, o + 3 * TILE_B);
                Bhf[np * 2 + 0][0] = h0; Bhf[np * 2 + 0][1] = h2;
                Bhf[np * 2 + 1][0] = h1; Bhf[np * 2 + 1][1] = h3;
                Blf[np * 2 + 0][0] = l0; Blf[np * 2 + 0][1] = l2;
                Blf[np * 2 + 1][0] = l1; Blf[np * 2 + 1][1] = l3;
            }
#pragma unroll
            for (int mi = 0; mi < 4; mi++)
#pragma unroll
                for (int ni = 0; ni < 4; ni++) {
                    mma16816(acc[mi][ni], Ahf[mi], Bhf[ni]);
                    mma16816(acc[mi][ni], Alf[mi], Bhf[ni]);
                    mma16816(acc[mi][ni], Ahf[mi], Blf[ni]);
                }
        }

        if (t == NCONV - 1) {
            // conv done: acc = elu(acc + b_conv); skip chunks then accumulate on top
#pragma unroll
            for (int ni = 0; ni < 4; ni++) {
                int col = warpN * 32 + ni * 8 + 2 * (lane & 3);
                float b0 = __ldg(bconv + col), b1 = __ldg(bconv + col + 1);
#pragma unroll
                for (int mi = 0; mi < 4; mi++) {
                    acc[mi][ni][0] = elu1(acc[mi][ni][0] + b0);
                    acc[mi][ni][1] = elu1(acc[mi][ni][1] + b1);
                    acc[mi][ni][2] = elu1(acc[mi][ni][2] + b0);
                    acc[mi][ni][3] = elu1(acc[mi][ni][3] + b1);
                }
            }
        }
    }

    // ---- epilogue: out = acc + b_skip ----
#pragma unroll
    for (int ni = 0; ni < 4; ni++) {
        int col = warpN * 32 + ni * 8 + 2 * (lane & 3);
        float b0 = __ldg(bskip + col), b1 = __ldg(bskip + col + 1);
#pragma unroll
        for (int mi = 0; mi < 4; mi++) {
            size_t r0 = mrow0 + warpM * 64 + mi * 16 + (lane >> 2);
            float2 v0 = make_float2(acc[mi][ni][0] + b0, acc[mi][ni][1] + b1);
            float2 v1 = make_float2(acc[mi][ni][2] + b0, acc[mi][ni][3] + b1);
            *(float2*)&out[r0 * Cc + col]       = v0;
            *(float2*)&out[(r0 + 8) * Cc + col] = v1;
        }
    }
}

// ---------------- launch ----------------
extern "C" void kernel_launch(void* const* d_in, const int* in_sizes, int n_in,
                              void* d_out, int out_size)
{
    const float* x   = (const float*)d_in[0];
    const int*   idx = (const int*)  d_in[1];
    const float* P   = (const float*)d_in[2];
    const float* Wc  = (const float*)d_in[3];
    const float* bc  = (const float*)d_in[4];
    const float* Ws  = (const float*)d_in[5];
    const float* bs  = (const float*)d_in[6];
    float* out = (float*)d_out;
    (void)in_sizes; (void)n_in; (void)out_size;

    cudaFuncSetAttribute(gemm_mma, cudaFuncAttributeMaxDynamicSharedMemorySize, SMEM_B);

    cvt_w<<<(Cc * Ffull + 255) / 256, 256>>>(Wc, Ws);
    cvt_x<<<(int)(((size_t)Mm * Cc / 4 + 255) / 256), 256>>>(x);
    build_flat<<<Nn, 128>>>(x, idx, P);
    gemm_mma<<<Mm / 128, 256, SMEM_B>>>(bc, bs, out);
}

// round 9
// speedup vs baseline: 4.2067x; 1.5493x over previous
#include <cuda_runtime.h>
#include <cuda_fp16.h>
#include <math.h>
#include <stdint.h>

// ---------------- problem constants ----------------
#define Bsz 16
#define Nn  16384
#define Cc  128            // C_IN == C_OUT
#define Ffull 1152         // 9 * 128
#define Mm  (Bsz * Nn)     // 262144 rows

// ---------------- static device scratch (fp16, single precision level) ----------------
__device__ __half g_flat_h[(size_t)Mm * Ffull];
__device__ __half g_x_h[(size_t)Mm * Cc];
__device__ __half g_Wc_h[Cc * Ffull];
__device__ __half g_Ws_h[Cc * Cc];

// ---------------- helpers ----------------
__device__ __forceinline__ uint32_t smem_u32(const void* p) {
    uint32_t a;
    asm("{ .reg .u64 t; cvta.to.shared.u64 t, %1; cvt.u32.u64 %0, t; }" : "=r"(a) : "l"(p));
    return a;
}
__device__ __forceinline__ void cp16(uint32_t dst, const void* src) {
    asm volatile("cp.async.cg.shared.global [%0], [%1], 16;" :: "r"(dst), "l"(src) : "memory");
}
#define CP_COMMIT() asm volatile("cp.async.commit_group;" ::: "memory")
#define CP_WAIT(n)  asm volatile("cp.async.wait_group %0;" :: "n"(n) : "memory")

__device__ __forceinline__ void ldsm4(uint32_t& d0, uint32_t& d1, uint32_t& d2, uint32_t& d3, uint32_t a) {
    asm volatile("ldmatrix.sync.aligned.m8n8.x4.shared.b16 {%0,%1,%2,%3}, [%4];"
                 : "=r"(d0), "=r"(d1), "=r"(d2), "=r"(d3) : "r"(a));
}
__device__ __forceinline__ void mma16816(float* c, const uint32_t* a, const uint32_t* b) {
    asm volatile("mma.sync.aligned.m16n8k16.row.col.f32.f16.f16.f32 "
                 "{%0,%1,%2,%3},{%4,%5,%6,%7},{%8,%9},{%0,%1,%2,%3};"
                 : "+f"(c[0]), "+f"(c[1]), "+f"(c[2]), "+f"(c[3])
                 : "r"(a[0]), "r"(a[1]), "r"(a[2]), "r"(a[3]), "r"(b[0]), "r"(b[1]));
}
__device__ __forceinline__ float elu1(float v) { return (v > 0.f) ? v : expm1f(v); }
__device__ __forceinline__ uint32_t h2u(__half2 h) { return *(uint32_t*)&h; }

// ---------------- pass 0: convert weights / x to fp16 ----------------
__global__ void cvt_w(const float* __restrict__ Wc, const float* __restrict__ Ws) {
    int i = blockIdx.x * 256 + threadIdx.x;
    if (i < Cc * Ffull) g_Wc_h[i] = __float2half_rn(Wc[i]);
    if (i < Cc * Cc)    g_Ws_h[i] = __float2half_rn(Ws[i]);
}
__global__ __launch_bounds__(256) void cvt_x(const float* __restrict__ x) {
    size_t i4 = (size_t)blockIdx.x * 256 + threadIdx.x;   // index over float4s
    if (i4 >= (size_t)Mm * Cc / 4) return;
    float4 v = *(const float4*)(x + i4 * 4);
    uint2 o;
    o.x = h2u(__float22half2_rn(make_float2(v.x, v.y)));
    o.y = h2u(__float22half2_rn(make_float2(v.z, v.w)));
    *(uint2*)(g_x_h + i4 * 4) = o;
}

// ---------------- pass 1: gather + P-mix + elu -> g_flat (fp16) ----------------
// 128 threads / node: c4 = (tid&31)*4 channel quad; tid>>5 -> batch quad.
__global__ __launch_bounds__(128) void build_flat(
    const float* __restrict__ x, const int* __restrict__ idx, const float* __restrict__ P)
{
    const int n = blockIdx.x;
    const int tid = threadIdx.x;
    const int c4 = (tid & 31) * 4;
    const int b0 = (tid >> 5) * 4;

    __shared__ float Ps[81];
    __shared__ int   is[9];
    if (tid < 81) Ps[tid] = P[(size_t)n * 81 + tid];
    if (tid < 9)  is[tid] = idx[n * 9 + tid];
    __syncthreads();
    int ir[9];
#pragma unroll
    for (int j = 0; j < 9; j++) ir[j] = is[j];

    for (int bb = 0; bb < 4; bb++) {
        const int b = b0 + bb;
        float4 nb[9];
#pragma unroll
        for (int j = 0; j < 9; j++)
            nb[j] = *(const float4*)&x[((size_t)b * Nn + ir[j]) * Cc + c4];
        const size_t base = ((size_t)b * Nn + n) * Ffull + c4;
#pragma unroll
        for (int k = 0; k < 9; k++) {
            float v0 = 0.f, v1 = 0.f, v2 = 0.f, v3 = 0.f;
#pragma unroll
            for (int j = 0; j < 9; j++) {
                float p = Ps[k * 9 + j];
                v0 = fmaf(p, nb[j].x, v0);
                v1 = fmaf(p, nb[j].y, v1);
                v2 = fmaf(p, nb[j].z, v2);
                v3 = fmaf(p, nb[j].w, v3);
            }
            uint2 o;
            o.x = h2u(__float22half2_rn(make_float2(elu1(v0), elu1(v1))));
            o.y = h2u(__float22half2_rn(make_float2(elu1(v2), elu1(v3))));
            *(uint2*)(g_flat_h + base + (size_t)k * Cc) = o;
        }
    }
}

// ---------------- pass 2: single-fp16 mma.sync GEMM, fused epilogue ----------------
// K-chunks of 64: 18 conv chunks (g_flat @ Wc^T), reg-level bias+elu, then 2
// skip chunks (x @ Ws^T) on top. 3-stage cp.async, 96KB smem -> 2 CTAs/SM.
#define NCH     20
#define NCONV   18
#define TILE_B  16384                 // 128 rows x 128 bytes (64 fp16)
#define STAGE_B (2 * TILE_B)          // A, B = 32KB
#define NSTAGE  3
#define SMEM_B  (NSTAGE * STAGE_B)    // 98304

// swizzled offset for (row r, 16B-granule g in 0..7), 128B rows
#define SWO(r, g) ((uint32_t)(r) * 128u + (uint32_t)((((g) ^ ((r) & 7))) << 4))

__global__ __launch_bounds__(256, 2) void gemm_mma(
    const float* __restrict__ bconv, const float* __restrict__ bskip,
    float* __restrict__ out)
{
    extern __shared__ char smem[];
    const uint32_t sb = smem_u32(smem);
    const int tid = threadIdx.x;
    const int lane = tid & 31, wid = tid >> 5;
    const int warpM = wid >> 2, warpN = wid & 3;      // 2 x 4 warp grid
    const size_t mrow0 = (size_t)blockIdx.x * 128;

    // ---- hoisted loader geometry ----
    const int lrw = tid >> 3, lgw = tid & 7;          // 32 rows x 8 granules per wave
    uint32_t sdst[4];
    const __half* aC[4]; const __half* bC[4];         // conv srcs
    const __half* aS[4]; const __half* bS[4];         // skip srcs
#pragma unroll
    for (int i = 0; i < 4; i++) {
        int r = i * 32 + lrw;
        sdst[i] = SWO(r, lgw);
        aC[i] = g_flat_h + (mrow0 + r) * (size_t)Ffull + lgw * 8;
        bC[i] = g_Wc_h   + (size_t)r * Ffull          + lgw * 8;
        aS[i] = g_x_h    + (mrow0 + r) * (size_t)Cc   + lgw * 8;
        bS[i] = g_Ws_h   + (size_t)r * Cc             + lgw * 8;
    }

    auto issue = [&](int t, int s) {
        const uint32_t st = sb + (uint32_t)s * STAGE_B;
        if (t < NCONV) {
            const int off = t * 64;
#pragma unroll
            for (int i = 0; i < 4; i++) {
                cp16(st + sdst[i],          aC[i] + off);
                cp16(st + sdst[i] + TILE_B, bC[i] + off);
            }
        } else {
            const int off = (t - NCONV) * 64;
#pragma unroll
            for (int i = 0; i < 4; i++) {
                cp16(st + sdst[i],          aS[i] + off);
                cp16(st + sdst[i] + TILE_B, bS[i] + off);
            }
        }
        CP_COMMIT();
    };

    // ---- fragment address components (swizzle recomputed cheaply per kk) ----
    const int lr = lane & 15, lg = lane >> 4;
    uint32_t arow[4], brow[2];
    int ax7[4], bx7[2];
#pragma unroll
    for (int mi = 0; mi < 4; mi++) {
        int r = warpM * 64 + mi * 16 + lr;
        arow[mi] = (uint32_t)r * 128u; ax7[mi] = r & 7;
    }
#pragma unroll
    for (int np = 0; np < 2; np++) {
        int r = warpN * 32 + np * 16 + lr;
        brow[np] = (uint32_t)r * 128u; bx7[np] = r & 7;
    }

    float acc[4][4][4];
#pragma unroll
    for (int mi = 0; mi < 4; mi++)
#pragma unroll
        for (int ni = 0; ni < 4; ni++)
#pragma unroll
            for (int j = 0; j < 4; j++) acc[mi][ni][j] = 0.f;

    issue(0, 0); issue(1, 1);

    for (int t = 0; t < NCH; t++) {
        if (t + 1 < NCH) CP_WAIT(1); else CP_WAIT(0);
        __syncthreads();
        if (t + 2 < NCH) issue(t + 2, (t + 2) % NSTAGE);   // overlaps compute below

        const uint32_t st = sb + (uint32_t)(t % NSTAGE) * STAGE_B;
#pragma unroll
        for (int kk = 0; kk < 4; kk++) {
            const int g = kk * 2 + lg;
            uint32_t Af[4][4], Bf[4][2];
#pragma unroll
            for (int mi = 0; mi < 4; mi++) {
                uint32_t o = st + arow[mi] + (uint32_t)((g ^ ax7[mi]) << 4);
                ldsm4(Af[mi][0], Af[mi][1], Af[mi][2], Af[mi][3], o);
            }
#pragma unroll
            for (int np = 0; np < 2; np++) {
                uint32_t o = st + TILE_B + brow[np] + (uint32_t)((g ^ bx7[np]) << 4);
                uint32_t h0, h1, h2, h3;
                ldsm4(h0, h1, h2, h3, o);
                Bf[np * 2 + 0][0] = h0; Bf[np * 2 + 0][1] = h2;
                Bf[np * 2 + 1][0] = h1; Bf[np * 2 + 1][1] = h3;
            }
#pragma unroll
            for (int mi = 0; mi < 4; mi++)
#pragma unroll
                for (int ni = 0; ni < 4; ni++)
                    mma16816(acc[mi][ni], Af[mi], Bf[ni]);
        }

        if (t == NCONV - 1) {
            // conv done: acc = elu(acc + b_conv); skip chunks then accumulate on top
#pragma unroll
            for (int ni = 0; ni < 4; ni++) {
                int col = warpN * 32 + ni * 8 + 2 * (lane & 3);
                float b0 = __ldg(bconv + col), b1 = __ldg(bconv + col + 1);
#pragma unroll
                for (int mi = 0; mi < 4; mi++) {
                    acc[mi][ni][0] = elu1(acc[mi][ni][0] + b0);
                    acc[mi][ni][1] = elu1(acc[mi][ni][1] + b1);
                    acc[mi][ni][2] = elu1(acc[mi][ni][2] + b0);
                    acc[mi][ni][3] = elu1(acc[mi][ni][3] + b1);
                }
            }
        }
    }

    // ---- epilogue: out = acc + b_skip ----
#pragma unroll
    for (int ni = 0; ni < 4; ni++) {
        int col = warpN * 32 + ni * 8 + 2 * (lane & 3);
        float b0 = __ldg(bskip + col), b1 = __ldg(bskip + col + 1);
#pragma unroll
        for (int mi = 0; mi < 4; mi++) {
            size_t r0 = mrow0 + warpM * 64 + mi * 16 + (lane >> 2);
            float2 v0 = make_float2(acc[mi][ni][0] + b0, acc[mi][ni][1] + b1);
            float2 v1 = make_float2(acc[mi][ni][2] + b0, acc[mi][ni][3] + b1);
            *(float2*)&out[r0 * Cc + col]       = v0;
            *(float2*)&out[(r0 + 8) * Cc + col] = v1;
        }
    }
}

// ---------------- launch ----------------
extern "C" void kernel_launch(void* const* d_in, const int* in_sizes, int n_in,
                              void* d_out, int out_size)
{
    const float* x   = (const float*)d_in[0];
    const int*   idx = (const int*)  d_in[1];
    const float* P   = (const float*)d_in[2];
    const float* Wc  = (const float*)d_in[3];
    const float* bc  = (const float*)d_in[4];
    const float* Ws  = (const float*)d_in[5];
    const float* bs  = (const float*)d_in[6];
    float* out = (float*)d_out;
    (void)in_sizes; (void)n_in; (void)out_size;

    cudaFuncSetAttribute(gemm_mma, cudaFuncAttributeMaxDynamicSharedMemorySize, SMEM_B);

    cvt_w<<<(Cc * Ffull + 255) / 256, 256>>>(Wc, Ws);
    cvt_x<<<(int)(((size_t)Mm * Cc / 4 + 255) / 256), 256>>>(x);
    build_flat<<<Nn, 128>>>(x, idx, P);
    gemm_mma<<<Mm / 128, 256, SMEM_B>>>(bc, bs, out);
}

// round 10
// speedup vs baseline: 5.2588x; 1.2501x over previous
#include <cuda_runtime.h>
#include <cuda_fp16.h>
#include <math.h>
#include <stdint.h>

// ---------------- problem constants ----------------
#define Bsz 16
#define Nn  16384
#define Cc  128            // C_IN == C_OUT
#define Ffull 1152         // 9 * 128
#define Mm  (Bsz * Nn)     // 262144 rows

// ---------------- static device scratch (fp16) ----------------
__device__ __half g_flat_h[(size_t)Mm * Ffull];
__device__ __half g_x_h[(size_t)Mm * Cc];
__device__ __half g_Wc_h[Cc * Ffull];
__device__ __half g_Ws_h[Cc * Cc];

// ---------------- helpers ----------------
__device__ __forceinline__ uint32_t smem_u32(const void* p) {
    uint32_t a;
    asm("{ .reg .u64 t; cvta.to.shared.u64 t, %1; cvt.u32.u64 %0, t; }" : "=r"(a) : "l"(p));
    return a;
}
__device__ __forceinline__ void cp16(uint32_t dst, const void* src) {
    asm volatile("cp.async.cg.shared.global [%0], [%1], 16;" :: "r"(dst), "l"(src) : "memory");
}
#define CP_COMMIT() asm volatile("cp.async.commit_group;" ::: "memory")
#define CP_WAIT(n)  asm volatile("cp.async.wait_group %0;" :: "n"(n) : "memory")

__device__ __forceinline__ void ldsm4(uint32_t& d0, uint32_t& d1, uint32_t& d2, uint32_t& d3, uint32_t a) {
    asm volatile("ldmatrix.sync.aligned.m8n8.x4.shared.b16 {%0,%1,%2,%3}, [%4];"
                 : "=r"(d0), "=r"(d1), "=r"(d2), "=r"(d3) : "r"(a));
}
__device__ __forceinline__ void mma16816(float* c, const uint32_t* a, const uint32_t* b) {
    asm volatile("mma.sync.aligned.m16n8k16.row.col.f32.f16.f16.f32 "
                 "{%0,%1,%2,%3},{%4,%5,%6,%7},{%8,%9},{%0,%1,%2,%3};"
                 : "+f"(c[0]), "+f"(c[1]), "+f"(c[2]), "+f"(c[3])
                 : "r"(a[0]), "r"(a[1]), "r"(a[2]), "r"(a[3]), "r"(b[0]), "r"(b[1]));
}
// fast elu: for v<0, exp(v)-1 via MUFU-based __expf. Absolute error ~2e-7 —
// negligible vs the fp16 rounding (abs ~2.4e-4 * |elem|) applied to the same values.
__device__ __forceinline__ float elu1(float v) { return (v > 0.f) ? v : (__expf(v) - 1.f); }
__device__ __forceinline__ uint32_t h2u(__half2 h) { return *(uint32_t*)&h; }

// ---------------- pass 0: convert weights / x to fp16 ----------------
__global__ void cvt_w(const float* __restrict__ Wc, const float* __restrict__ Ws) {
    int i = blockIdx.x * 256 + threadIdx.x;
    if (i < Cc * Ffull) g_Wc_h[i] = __float2half_rn(Wc[i]);
    if (i < Cc * Cc)    g_Ws_h[i] = __float2half_rn(Ws[i]);
}
__global__ __launch_bounds__(256) void cvt_x(const float* __restrict__ x) {
    size_t i4 = (size_t)blockIdx.x * 256 + threadIdx.x;   // index over float4s
    if (i4 >= (size_t)Mm * Cc / 4) return;
    float4 v = *(const float4*)(x + i4 * 4);
    uint2 o;
    o.x = h2u(__float22half2_rn(make_float2(v.x, v.y)));
    o.y = h2u(__float22half2_rn(make_float2(v.z, v.w)));
    *(uint2*)(g_x_h + i4 * 4) = o;
}

// ---------------- pass 1: gather(fp16) + P-mix + elu -> g_flat (fp16) ----------------
// 256 threads / node: c4 = (tid&31)*4 channel quad; tid>>5 -> batch (2 per thread).
__global__ __launch_bounds__(256) void build_flat(
    const int* __restrict__ idx, const float* __restrict__ P)
{
    const int n = blockIdx.x;
    const int tid = threadIdx.x;
    const int c4 = (tid & 31) * 4;
    const int bq = tid >> 5;                 // 0..7

    __shared__ float Ps[81];
    __shared__ int   is[9];
    if (tid < 81) Ps[tid] = P[(size_t)n * 81 + tid];
    if (tid < 9)  is[tid] = idx[n * 9 + tid];
    __syncthreads();
    int ir[9];
#pragma unroll
    for (int j = 0; j < 9; j++) ir[j] = is[j];

#pragma unroll
    for (int bb = 0; bb < 2; bb++) {
        const int b = bq + bb * 8;
        float4 nb[9];
#pragma unroll
        for (int j = 0; j < 9; j++) {
            uint2 raw = *(const uint2*)&g_x_h[((size_t)b * Nn + ir[j]) * Cc + c4];
            float2 f01 = __half22float2(*(__half2*)&raw.x);
            float2 f23 = __half22float2(*(__half2*)&raw.y);
            nb[j] = make_float4(f01.x, f01.y, f23.x, f23.y);
        }
        const size_t base = ((size_t)b * Nn + n) * Ffull + c4;
#pragma unroll
        for (int k = 0; k < 9; k++) {
            float v0 = 0.f, v1 = 0.f, v2 = 0.f, v3 = 0.f;
#pragma unroll
            for (int j = 0; j < 9; j++) {
                float p = Ps[k * 9 + j];
                v0 = fmaf(p, nb[j].x, v0);
                v1 = fmaf(p, nb[j].y, v1);
                v2 = fmaf(p, nb[j].z, v2);
                v3 = fmaf(p, nb[j].w, v3);
            }
            uint2 o;
            o.x = h2u(__float22half2_rn(make_float2(elu1(v0), elu1(v1))));
            o.y = h2u(__float22half2_rn(make_float2(elu1(v2), elu1(v3))));
            *(uint2*)(g_flat_h + base + (size_t)k * Cc) = o;
        }
    }
}

// ---------------- pass 2: single-fp16 mma.sync GEMM, fused epilogue ----------------
#define NCH     20
#define NCONV   18
#define TILE_B  16384                 // 128 rows x 128 bytes (64 fp16)
#define STAGE_B (2 * TILE_B)          // A, B = 32KB
#define NSTAGE  3
#define SMEM_B  (NSTAGE * STAGE_B)    // 98304

// swizzled offset for (row r, 16B-granule g in 0..7), 128B rows
#define SWO(r, g) ((uint32_t)(r) * 128u + (uint32_t)((((g) ^ ((r) & 7))) << 4))

__global__ __launch_bounds__(256, 2) void gemm_mma(
    const float* __restrict__ bconv, const float* __restrict__ bskip,
    float* __restrict__ out)
{
    extern __shared__ char smem[];
    const uint32_t sb = smem_u32(smem);
    const int tid = threadIdx.x;
    const int lane = tid & 31, wid = tid >> 5;
    const int warpM = wid >> 2, warpN = wid & 3;      // 2 x 4 warp grid
    const size_t mrow0 = (size_t)blockIdx.x * 128;

    // ---- loader: precomputed dsts + advancing src pointers (minimal per-issue alu) ----
    const int lrw = tid >> 3, lgw = tid & 7;          // 32 rows x 8 granules per wave
    uint32_t sdst[4];
    const __half* pa[4]; const __half* pb[4];         // advancing conv srcs
    const __half* aS[4]; const __half* bS[4];         // skip srcs
#pragma unroll
    for (int i = 0; i < 4; i++) {
        int r = i * 32 + lrw;
        sdst[i] = SWO(r, lgw);
        pa[i] = g_flat_h + (mrow0 + r) * (size_t)Ffull + lgw * 8;
        pb[i] = g_Wc_h   + (size_t)r * Ffull          + lgw * 8;
        aS[i] = g_x_h    + (mrow0 + r) * (size_t)Cc   + lgw * 8;
        bS[i] = g_Ws_h   + (size_t)r * Cc             + lgw * 8;
    }

    auto issue = [&](int t, int s) {
        const uint32_t st = sb + (uint32_t)s * STAGE_B;
        if (t < NCONV) {
#pragma unroll
            for (int i = 0; i < 4; i++) {
                cp16(st + sdst[i],          pa[i]);
                cp16(st + sdst[i] + TILE_B, pb[i]);
                pa[i] += 64; pb[i] += 64;
            }
        } else {
            const int off = (t - NCONV) * 64;
#pragma unroll
            for (int i = 0; i < 4; i++) {
                cp16(st + sdst[i],          aS[i] + off);
                cp16(st + sdst[i] + TILE_B, bS[i] + off);
            }
        }
        CP_COMMIT();
    };

    // ---- fragment address components ----
    const int lr = lane & 15, lg = lane >> 4;
    uint32_t arow[4], brow[2];
    int ax7[4], bx7[2];
#pragma unroll
    for (int mi = 0; mi < 4; mi++) {
        int r = warpM * 64 + mi * 16 + lr;
        arow[mi] = (uint32_t)r * 128u; ax7[mi] = r & 7;
    }
#pragma unroll
    for (int np = 0; np < 2; np++) {
        int r = warpN * 32 + np * 16 + lr;
        brow[np] = (uint32_t)r * 128u; bx7[np] = r & 7;
    }

    float acc[4][4][4];
#pragma unroll
    for (int mi = 0; mi < 4; mi++)
#pragma unroll
        for (int ni = 0; ni < 4; ni++)
#pragma unroll
            for (int j = 0; j < 4; j++) acc[mi][ni][j] = 0.f;

    issue(0, 0); issue(1, 1);

    for (int t = 0; t < NCH; t++) {
        if (t + 1 < NCH) CP_WAIT(1); else CP_WAIT(0);
        __syncthreads();
        if (t + 2 < NCH) issue(t + 2, (t + 2) % NSTAGE);   // overlaps compute below

        const uint32_t st = sb + (uint32_t)(t % NSTAGE) * STAGE_B;
#pragma unroll
        for (int kk = 0; kk < 4; kk++) {
            const int g = kk * 2 + lg;
            uint32_t Af[4][4], Bf[4][2];
#pragma unroll
            for (int mi = 0; mi < 4; mi++) {
                uint32_t o = st + arow[mi] + (uint32_t)((g ^ ax7[mi]) << 4);
                ldsm4(Af[mi][0], Af[mi][1], Af[mi][2], Af[mi][3], o);
            }
#pragma unroll
            for (int np = 0; np < 2; np++) {
                uint32_t o = st + TILE_B + brow[np] + (uint32_t)((g ^ bx7[np]) << 4);
                uint32_t h0, h1, h2, h3;
                ldsm4(h0, h1, h2, h3, o);
                Bf[np * 2 + 0][0] = h0; Bf[np * 2 + 0][1] = h2;
                Bf[np * 2 + 1][0] = h1; Bf[np * 2 + 1][1] = h3;
            }
#pragma unroll
            for (int mi = 0; mi < 4; mi++)
#pragma unroll
                for (int ni = 0; ni < 4; ni++)
                    mma16816(acc[mi][ni], Af[mi], Bf[ni]);
        }

        if (t == NCONV - 1) {
            // conv done: acc = elu(acc + b_conv); skip chunks then accumulate on top
#pragma unroll
            for (int ni = 0; ni < 4; ni++) {
                int col = warpN * 32 + ni * 8 + 2 * (lane & 3);
                float b0 = __ldg(bconv + col), b1 = __ldg(bconv + col + 1);
#pragma unroll
                for (int mi = 0; mi < 4; mi++) {
                    acc[mi][ni][0] = elu1(acc[mi][ni][0] + b0);
                    acc[mi][ni][1] = elu1(acc[mi][ni][1] + b1);
                    acc[mi][ni][2] = elu1(acc[mi][ni][2] + b0);
                    acc[mi][ni][3] = elu1(acc[mi][ni][3] + b1);
                }
            }
        }
    }

    // ---- epilogue: out = acc + b_skip ----
#pragma unroll
    for (int ni = 0; ni < 4; ni++) {
        int col = warpN * 32 + ni * 8 + 2 * (lane & 3);
        float b0 = __ldg(bskip + col), b1 = __ldg(bskip + col + 1);
#pragma unroll
        for (int mi = 0; mi < 4; mi++) {
            size_t r0 = mrow0 + warpM * 64 + mi * 16 + (lane >> 2);
            float2 v0 = make_float2(acc[mi][ni][0] + b0, acc[mi][ni][1] + b1);
            float2 v1 = make_float2(acc[mi][ni][2] + b0, acc[mi][ni][3] + b1);
            *(float2*)&out[r0 * Cc + col]       = v0;
            *(float2*)&out[(r0 + 8) * Cc + col] = v1;
        }
    }
}

// ---------------- launch ----------------
extern "C" void kernel_launch(void* const* d_in, const int* in_sizes, int n_in,
                              void* d_out, int out_size)
{
    const float* x   = (const float*)d_in[0];
    const int*   idx = (const int*)  d_in[1];
    const float* P   = (const float*)d_in[2];
    const float* Wc  = (const float*)d_in[3];
    const float* bc  = (const float*)d_in[4];
    const float* Ws  = (const float*)d_in[5];
    const float* bs  = (const float*)d_in[6];
    float* out = (float*)d_out;
    (void)in_sizes; (void)n_in; (void)out_size;

    cudaFuncSetAttribute(gemm_mma, cudaFuncAttributeMaxDynamicSharedMemorySize, SMEM_B);

    cvt_x<<<(int)(((size_t)Mm * Cc / 4 + 255) / 256), 256>>>(x);   // must precede build_flat
    cvt_w<<<(Cc * Ffull + 255) / 256, 256>>>(Wc, Ws);
    build_flat<<<Nn, 256>>>(idx, P);
    gemm_mma<<<Mm / 128, 256, SMEM_B>>>(bc, bs, out);
}